// round 15
// baseline (speedup 1.0000x reference)
#include <cuda_runtime.h>
#include <cuda_fp16.h>
#include <stdint.h>
#include <math.h>

// CommNetWork fused, fp16 2-term split mma.sync (m16n8k16.f32.f16.f16.f32).
// R14: TWO batches per CTA (M=128 rows), grid=128 -> single wave, and every
// staged weight chunk feeds both batches (staging+barriers amortized 2x).
// B=256, N=64 agents, D_IN=128, H0=256, H1=256, H2=64.
// Precision: activations fp16; weights w = wh + wl (both fp16), 2 MMA terms.
// Comm factorization: c=(S-h)/64; W_ih pre-scaled by -1/64 so gi and gh share
// one accumulator; per-batch S-term t[b][col] accumulated from staged chunks.
// 16 warps in 2(M)x8(N) grid: each warp 64 rows x 32 cols (MT=4, NT=4, acc[64]).

#define ROWS    128   // 2 batches x 64 agents
#define NTHREADS 512
#define LDA_ACT 264   // fp16 elems per activation row (256+8 pad)
#define LDW     40    // fp16 elems per weight-chunk row (32+8 pad)
#define KCH     32    // k per staged chunk (double buffered)

#define OFF_ENC 0
#define OFF_OBS 32768
#define OFF_IH  98304
#define OFF_HH  294912
#define OFF_VAL 491520
#define OFF_DEC 557056
#define W_TOTAL 573440

__device__ __align__(16) __half g_whi[W_TOTAL];
__device__ __align__(16) __half g_wlo[W_TOTAL];

struct Smem {
    __half a1[ROWS * LDA_ACT];     // 67584 B
    __half a2[ROWS * LDA_ACT];     // 67584 B
    __half wh[2][256 * LDW];       // 40960 B
    __half wl[2][256 * LDW];       // 40960 B
    float S[512];                  // [2][256] per-batch column sums
    float t[512];                  // [2][256] per-batch comm term
};  // 221184 bytes

// ------------------------- weight conversion pre-pass -------------------
__global__ void conv_weights(const float* __restrict__ enc, const float* __restrict__ obsw,
                             const float* __restrict__ ih,  const float* __restrict__ hh,
                             const float* __restrict__ val, const float* __restrict__ dec)
{
    int i = blockIdx.x * blockDim.x + threadIdx.x;
    if (i >= W_TOTAL) return;
    const float* src;
    int off;
    float scale = 1.0f;
    if (i < OFF_OBS)      { src = enc;  off = i; }
    else if (i < OFF_IH)  { src = obsw; off = i - OFF_OBS; }
    else if (i < OFF_HH)  { src = ih;   off = i - OFF_IH; scale = -0.015625f; }
    else if (i < OFF_VAL) { src = hh;   off = i - OFF_HH; }
    else if (i < OFF_DEC) { src = val;  off = i - OFF_VAL; }
    else                  { src = dec;  off = i - OFF_DEC; }
    float v = src[off] * scale;
    __half h = __float2half_rn(v);
    g_whi[i] = h;
    g_wlo[i] = __float2half_rn(v - __half2float(h));
}

// ------------------------- device helpers --------------------------------
__device__ __forceinline__ float sigm(float x) { return 1.0f / (1.0f + __expf(-x)); }

__device__ __forceinline__ void cp16(void* dst, const void* src) {
    uint32_t d = (uint32_t)__cvta_generic_to_shared(dst);
    asm volatile("cp.async.cg.shared.global [%0], [%1], 16;\n" :: "r"(d), "l"(src));
}
__device__ __forceinline__ void cp_commit() { asm volatile("cp.async.commit_group;\n" ::); }
__device__ __forceinline__ void cp_wait1()  { asm volatile("cp.async.wait_group 1;\n" ::); }
__device__ __forceinline__ void cp_wait0()  { asm volatile("cp.async.wait_group 0;\n" ::); }

__device__ __forceinline__ void mma_f16(float* d,
                                        uint32_t a0, uint32_t a1, uint32_t a2, uint32_t a3,
                                        uint32_t b0, uint32_t b1)
{
    asm volatile("mma.sync.aligned.m16n8k16.row.col.f32.f16.f16.f32 "
                 "{%0,%1,%2,%3}, {%4,%5,%6,%7}, {%8,%9}, {%0,%1,%2,%3};\n"
                 : "+f"(d[0]), "+f"(d[1]), "+f"(d[2]), "+f"(d[3])
                 : "r"(a0), "r"(a1), "r"(a2), "r"(a3), "r"(b0), "r"(b1));
}

// stage one [nrows x 32k] hi+lo weight chunk (row = 64B = 4x16B segs)
__device__ __forceinline__ void stage(Smem& s, int buf,
                                      const __half* __restrict__ ghi,
                                      const __half* __restrict__ glo,
                                      int col0, int Ksrc, int k0, int nrows, int tid)
{
    int total = nrows * 4;
    for (int idx = tid; idx < total; idx += NTHREADS) {
        int r = idx >> 2;
        int seg = idx & 3;
        size_t so = (size_t)(col0 + r) * Ksrc + k0 + seg * 8;
        cp16(&s.wh[buf][r * LDW + seg * 8], ghi + so);
        cp16(&s.wl[buf][r * LDW + seg * 8], glo + so);
    }
    cp_commit();
}

// one 32-k chunk: acc += A*Wh + A*Wl   (MT m16-tiles from tile m0, NT n8-tiles)
template<int NT, int MT>
__device__ __forceinline__ void mma_chunk(const __half* __restrict__ ah,
                                          const __half* __restrict__ wh,
                                          const __half* __restrict__ wl,
                                          int kbase, int m0, int n0, int g, int t4, float* acc)
{
#pragma unroll
    for (int ks = 0; ks < 2; ++ks) {
        int klA = kbase + ks * 16 + 2 * t4;
        int klW = ks * 16 + 2 * t4;
        uint32_t bh0[NT], bh1[NT], bl0[NT], bl1[NT];
#pragma unroll
        for (int nt = 0; nt < NT; ++nt) {
            int wrow = (n0 + nt * 8 + g) * LDW + klW;
            bh0[nt] = *(const uint32_t*)&wh[wrow];
            bh1[nt] = *(const uint32_t*)&wh[wrow + 8];
            bl0[nt] = *(const uint32_t*)&wl[wrow];
            bl1[nt] = *(const uint32_t*)&wl[wrow + 8];
        }
#pragma unroll
        for (int mt = 0; mt < MT; ++mt) {
            int ab = ((m0 + mt) * 16 + g) * LDA_ACT + klA;
            uint32_t A0 = *(const uint32_t*)&ah[ab];
            uint32_t A1 = *(const uint32_t*)&ah[ab + 8 * LDA_ACT];
            uint32_t A2 = *(const uint32_t*)&ah[ab + 8];
            uint32_t A3 = *(const uint32_t*)&ah[ab + 8 * LDA_ACT + 8];
#pragma unroll
            for (int nt = 0; nt < NT; ++nt) {
                float* d = acc + (mt * NT + nt) * 4;
                mma_f16(d, A0, A1, A2, A3, bh0[nt], bh1[nt]);
                mma_f16(d, A0, A1, A2, A3, bl0[nt], bl1[nt]);
            }
        }
    }
}

// TACC: accumulate per-batch t[b][col] from the staged hi+lo chunk.
template<int NT, int MT, bool TACC>
__device__ __forceinline__ void gemm_pass(Smem& s,
                                          const __half* __restrict__ ah,
                                          const __half* __restrict__ ghi,
                                          const __half* __restrict__ glo,
                                          int col0, int Ksrc, int Kdim, int nrows,
                                          int m0, int n0, int g, int t4, int tid, float* acc)
{
    const int nch = Kdim / KCH;
    stage(s, 0, ghi, glo, col0, Ksrc, 0, nrows, tid);
    for (int c = 0; c < nch; ++c) {
        int cur = c & 1;
        bool more = (c + 1 < nch);
        if (more) {
            stage(s, 1 - cur, ghi, glo, col0, Ksrc, (c + 1) * KCH, nrows, tid);
            cp_wait1();
        } else {
            cp_wait0();
        }
        __syncthreads();
        if (TACC) {
            int b = tid >> 8;          // batch 0/1
            int col = tid & 255;
            float sum = 0.0f;
            const __half* w1 = &s.wh[cur][col * LDW];
            const __half* w2 = &s.wl[cur][col * LDW];
#pragma unroll
            for (int kk = 0; kk < KCH; ++kk) {
                sum += s.S[b * 256 + c * KCH + kk] *
                       (__half2float(w1[kk]) + __half2float(w2[kk]));
            }
            s.t[b * 256 + col] += sum;
        }
        mma_chunk<NT, MT>(ah, s.wh[cur], s.wl[cur], c * KCH, m0, n0, g, t4, acc);
        __syncthreads();
    }
}

__device__ __forceinline__ void store_h2(__half* a, int row, int col, float v0, float v1)
{
    __half2 p;
    p.x = __float2half_rn(v0);
    p.y = __float2half_rn(v1);
    *reinterpret_cast<__half2*>(&a[row * LDA_ACT + col]) = p;
}

__device__ __forceinline__ float2 load_h2(const __half* a, int row, int col)
{
    __half2 p = *reinterpret_cast<const __half2*>(&a[row * LDA_ACT + col]);
    float2 r;
    r.x = __half2float(p.x);
    r.y = __half2float(p.y);
    return r;
}

__device__ __forceinline__ void zero64(float* a)
{
#pragma unroll
    for (int i = 0; i < 64; ++i) { a[i] = 0.0f; }
}

// ------------------------- main fused kernel -----------------------------
__global__ void __launch_bounds__(NTHREADS, 1)
commnet_mma_kernel(const float* __restrict__ obs,
                   const float* __restrict__ b_enc, const float* __restrict__ b_obs,
                   const float* __restrict__ b_ih,  const float* __restrict__ b_hh,
                   const float* __restrict__ b_val, const float* __restrict__ b_dec,
                   float* __restrict__ out)
{
    extern __shared__ char smem_raw[];
    Smem& s = *reinterpret_cast<Smem*>(smem_raw);

    const int tid  = threadIdx.x;
    const int bid  = blockIdx.x;        // 0..127, covers batches 2*bid, 2*bid+1
    const int wid  = tid >> 5;
    const int lane = tid & 31;
    const int g    = lane >> 2;
    const int t4   = lane & 3;
    const int mg   = wid & 1;           // M half: rows mg*64..mg*64+63
    const int ng   = wid >> 1;          // 0..7: cols ng*32..ng*32+31
    const int m0g  = mg * 4;            // first m16-tile
    const int n0g  = ng * 32;           // col base

    float acc[64];

    // ---- P1: load obs [2 batches x 64 x 128] -> a1 fp16 ----
    {
        for (int idx = tid; idx < ROWS * 128; idx += NTHREADS) {
            int r = idx >> 7;
            int k = idx & 127;
            float v = obs[((size_t)(bid * 2 + (r >> 6)) * 64 + (r & 63)) * 128 + k];
            s.a1[r * LDA_ACT + k] = __float2half_rn(v);
        }
    }
    __syncthreads();

    // ---- P2: x = relu(obs @ W_enc^T + b_enc) -> a2 ----
    zero64(acc);
    gemm_pass<4, 4, false>(s, s.a1, g_whi + OFF_ENC, g_wlo + OFF_ENC,
                           0, 128, 128, 256, m0g, n0g, g, t4, tid, acc);
    for (int mt = 0; mt < 4; ++mt) {
        for (int nt = 0; nt < 4; ++nt) {
            int col = n0g + nt * 8 + 2 * t4;
            int r0 = (m0g + mt) * 16 + g;
            const float* d = acc + (mt * 4 + nt) * 4;
            float b0 = __ldg(&b_enc[col]);
            float b1 = __ldg(&b_enc[col + 1]);
            store_h2(s.a2, r0, col, fmaxf(d[0] + b0, 0.0f), fmaxf(d[1] + b1, 0.0f));
            store_h2(s.a2, r0 + 8, col, fmaxf(d[2] + b0, 0.0f), fmaxf(d[3] + b1, 0.0f));
        }
    }

    // ---- P3: h = x @ W_obs^T + b_obs -> a1 ----
    zero64(acc);
    gemm_pass<4, 4, false>(s, s.a2, g_whi + OFF_OBS, g_wlo + OFF_OBS,
                           0, 256, 256, 256, m0g, n0g, g, t4, tid, acc);
    for (int mt = 0; mt < 4; ++mt) {
        for (int nt = 0; nt < 4; ++nt) {
            int col = n0g + nt * 8 + 2 * t4;
            int r0 = (m0g + mt) * 16 + g;
            const float* d = acc + (mt * 4 + nt) * 4;
            float b0 = __ldg(&b_obs[col]);
            float b1 = __ldg(&b_obs[col + 1]);
            store_h2(s.a1, r0, col, d[0] + b0, d[1] + b1);
            store_h2(s.a1, r0 + 8, col, d[2] + b0, d[3] + b1);
        }
    }
    __syncthreads();

    // ---- P4: per-batch S = column sums of h; zero t ----
    {
        int b = tid >> 8;
        int f = tid & 255;
        float sum = 0.0f;
#pragma unroll 8
        for (int r = 0; r < 64; ++r) {
            sum += __half2float(s.a1[(b * 64 + r) * LDA_ACT + f]);
        }
        s.S[tid] = sum;
        s.t[tid] = 0.0f;
    }
    __syncthreads();

    // ======== P5 GRU (r, n, z; fragments round-trip through a2) ========

    // r gate
    zero64(acc);
    gemm_pass<4, 4, false>(s, s.a1, g_whi + OFF_HH, g_wlo + OFF_HH,
                           0, 256, 256, 256, m0g, n0g, g, t4, tid, acc);
    gemm_pass<4, 4, true>(s, s.a1, g_whi + OFF_IH, g_wlo + OFF_IH,
                          0, 256, 256, 256, m0g, n0g, g, t4, tid, acc);
    for (int mt = 0; mt < 4; ++mt) {
        for (int nt = 0; nt < 4; ++nt) {
            int col = n0g + nt * 8 + 2 * t4;
            int r0 = (m0g + mt) * 16 + g;
            int bh = r0 >> 6;
            float* d = acc + (mt * 4 + nt) * 4;
            float c0 = -s.t[bh * 256 + col] + __ldg(&b_ih[col]) + __ldg(&b_hh[col]);
            float c1 = -s.t[bh * 256 + col + 1] + __ldg(&b_ih[col + 1]) + __ldg(&b_hh[col + 1]);
            store_h2(s.a2, r0, col, sigm(d[0] + c0), sigm(d[1] + c1));
            store_h2(s.a2, r0 + 8, col, sigm(d[2] + c0), sigm(d[3] + c1));
        }
    }
    __syncthreads();
    s.t[tid] = 0.0f;

    // n gate
    zero64(acc);
    gemm_pass<4, 4, false>(s, s.a1, g_whi + OFF_HH, g_wlo + OFF_HH,
                           512, 256, 256, 256, m0g, n0g, g, t4, tid, acc);
    for (int mt = 0; mt < 4; ++mt) {
        for (int nt = 0; nt < 4; ++nt) {
            int col = n0g + nt * 8 + 2 * t4;
            int r0 = (m0g + mt) * 16 + g;
            float* d = acc + (mt * 4 + nt) * 4;
            float b0 = __ldg(&b_hh[512 + col]);
            float b1 = __ldg(&b_hh[512 + col + 1]);
            float2 ra = load_h2(s.a2, r0, col);
            float2 rb = load_h2(s.a2, r0 + 8, col);
            d[0] = ra.x * (d[0] + b0);
            d[1] = ra.y * (d[1] + b1);
            d[2] = rb.x * (d[2] + b0);
            d[3] = rb.y * (d[3] + b1);
        }
    }
    gemm_pass<4, 4, true>(s, s.a1, g_whi + OFF_IH, g_wlo + OFF_IH,
                          512, 256, 256, 256, m0g, n0g, g, t4, tid, acc);
    for (int mt = 0; mt < 4; ++mt) {
        for (int nt = 0; nt < 4; ++nt) {
            int col = n0g + nt * 8 + 2 * t4;
            int r0 = (m0g + mt) * 16 + g;
            int bh = r0 >> 6;
            float* d = acc + (mt * 4 + nt) * 4;
            float c0 = -s.t[bh * 256 + col] + __ldg(&b_ih[512 + col]);
            float c1 = -s.t[bh * 256 + col + 1] + __ldg(&b_ih[512 + col + 1]);
            store_h2(s.a2, r0, col, tanhf(d[0] + c0), tanhf(d[1] + c1));
            store_h2(s.a2, r0 + 8, col, tanhf(d[2] + c0), tanhf(d[3] + c1));
        }
    }
    __syncthreads();
    s.t[tid] = 0.0f;

    // z gate + blend: h_new = (1-z)*n + z*h_old -> a2
    zero64(acc);
    gemm_pass<4, 4, false>(s, s.a1, g_whi + OFF_HH, g_wlo + OFF_HH,
                           256, 256, 256, 256, m0g, n0g, g, t4, tid, acc);
    gemm_pass<4, 4, true>(s, s.a1, g_whi + OFF_IH, g_wlo + OFF_IH,
                          256, 256, 256, 256, m0g, n0g, g, t4, tid, acc);
    for (int mt = 0; mt < 4; ++mt) {
        for (int nt = 0; nt < 4; ++nt) {
            int col = n0g + nt * 8 + 2 * t4;
            int r0 = (m0g + mt) * 16 + g;
            int bh = r0 >> 6;
            float* d = acc + (mt * 4 + nt) * 4;
            float c0 = -s.t[bh * 256 + col] + __ldg(&b_ih[256 + col]) + __ldg(&b_hh[256 + col]);
            float c1 = -s.t[bh * 256 + col + 1] + __ldg(&b_ih[256 + col + 1]) + __ldg(&b_hh[256 + col + 1]);
            float z0 = sigm(d[0] + c0);
            float z1 = sigm(d[1] + c1);
            float z2 = sigm(d[2] + c0);
            float z3 = sigm(d[3] + c1);
            float2 na = load_h2(s.a2, r0, col);
            float2 nb = load_h2(s.a2, r0 + 8, col);
            float2 ha = load_h2(s.a1, r0, col);
            float2 hb = load_h2(s.a1, r0 + 8, col);
            store_h2(s.a2, r0, col,
                     (1.0f - z0) * na.x + z0 * ha.x,
                     (1.0f - z1) * na.y + z1 * ha.y);
            store_h2(s.a2, r0 + 8, col,
                     (1.0f - z2) * nb.x + z2 * hb.x,
                     (1.0f - z3) * nb.y + z3 * hb.y);
        }
    }

    // ---- P6: v = h_new @ W_val^T + b_val -> a1 ----
    zero64(acc);
    gemm_pass<4, 4, false>(s, s.a2, g_whi + OFF_VAL, g_wlo + OFF_VAL,
                           0, 256, 256, 256, m0g, n0g, g, t4, tid, acc);
    for (int mt = 0; mt < 4; ++mt) {
        for (int nt = 0; nt < 4; ++nt) {
            int col = n0g + nt * 8 + 2 * t4;
            int r0 = (m0g + mt) * 16 + g;
            const float* d = acc + (mt * 4 + nt) * 4;
            float b0 = __ldg(&b_val[col]);
            float b1 = __ldg(&b_val[col + 1]);
            store_h2(s.a1, r0, col, d[0] + b0, d[1] + b1);
            store_h2(s.a1, r0 + 8, col, d[2] + b0, d[3] + b1);
        }
    }

    // ---- P7: out = v @ W_dec^T + b_dec (64 cols; 16 warps in 2(M)x8(N)) ----
    {
        float ad[16];
#pragma unroll
        for (int i = 0; i < 16; ++i) { ad[i] = 0.0f; }
        int n0d = ng * 8;               // 8 cols per warp (NT=1)
        gemm_pass<1, 4, false>(s, s.a1, g_whi + OFF_DEC, g_wlo + OFF_DEC,
                               0, 256, 256, 64, m0g, n0d, g, t4, tid, ad);
        int col = n0d + 2 * t4;
        float b0 = __ldg(&b_dec[col]);
        float b1 = __ldg(&b_dec[col + 1]);
        for (int mt = 0; mt < 4; ++mt) {
            int r0 = (m0g + mt) * 16 + g;
            const float* d = ad + mt * 4;
            float* ob = out + ((size_t)(bid * 2 + (r0 >> 6)) * 64 + (r0 & 63)) * 64;
            float2 o0 = make_float2(d[0] + b0, d[1] + b1);
            *reinterpret_cast<float2*>(&ob[col]) = o0;
            int r1 = r0 + 8;
            float* ob1 = out + ((size_t)(bid * 2 + (r1 >> 6)) * 64 + (r1 & 63)) * 64;
            float2 o1 = make_float2(d[2] + b0, d[3] + b1);
            *reinterpret_cast<float2*>(&ob1[col]) = o1;
        }
    }
}

extern "C" void kernel_launch(void* const* d_in, const int* in_sizes, int n_in,
                              void* d_out, int out_size)
{
    const float* obs   = (const float*)d_in[0];
    const float* W_enc = (const float*)d_in[1];
    const float* b_enc = (const float*)d_in[2];
    const float* W_obs = (const float*)d_in[3];
    const float* b_obs = (const float*)d_in[4];
    const float* W_ih  = (const float*)d_in[5];
    const float* b_ih  = (const float*)d_in[6];
    const float* W_hh  = (const float*)d_in[7];
    const float* b_hh  = (const float*)d_in[8];
    const float* W_val = (const float*)d_in[9];
    const float* b_val = (const float*)d_in[10];
    const float* W_dec = (const float*)d_in[11];
    const float* b_dec = (const float*)d_in[12];
    float* out = (float*)d_out;
    (void)in_sizes; (void)n_in; (void)out_size;

    conv_weights<<<(W_TOTAL + 255) / 256, 256>>>(W_enc, W_obs, W_ih, W_hh, W_val, W_dec);

    cudaFuncSetAttribute(commnet_mma_kernel,
                         cudaFuncAttributeMaxDynamicSharedMemorySize, (int)sizeof(Smem));
    commnet_mma_kernel<<<128, NTHREADS, sizeof(Smem)>>>(
        obs, b_enc, b_obs, b_ih, b_hh, b_val, b_dec, out);
}

// round 16
// speedup vs baseline: 2.9992x; 2.9992x over previous
#include <cuda_runtime.h>
#include <cuda_fp16.h>
#include <stdint.h>
#include <math.h>

// CommNetWork fused, fp16 2-term split mma.sync (m16n8k16.f32.f16.f16.f32).
// R16: NO smem weight staging. Weights are pre-swizzled into fragment-major
// layout (8B per lane per n8-tile per k16-step, coalesced 256B/warp) and
// streamed global->register (L2-resident, shared by all CTAs). This removes
// all cp.async, all intra-pass barriers (76 -> 7 total) and the chunk-loop
// lockstep that dominated R13's non-tensor time.
// M=64 (one batch/CTA), 512 threads, 16 warps x (64 rows x 16 cols), acc[32].
// Precision: activations fp16; weights w = wh + wl (both fp16), 2 MMA terms.
// Comm: c=(S-h)/64; W_ih pre-scaled by -1/64; t[col]=S.W' precomputed once.

#define ROWS    64
#define NTHREADS 512
#define LDA_ACT 264   // fp16 elems per activation row (256+8 pad)

#define OFF_ENC 0
#define OFF_OBS 32768
#define OFF_IH  98304
#define OFF_HH  294912
#define OFF_VAL 491520
#define OFF_DEC 557056
#define W_TOTAL 573440

__device__ __align__(16) __half g_whi[W_TOTAL];   // row-major (for t precompute)
__device__ __align__(16) __half g_wlo[W_TOTAL];
__device__ __align__(16) __half g_fhi[W_TOTAL];   // fragment-major (for MMA)
__device__ __align__(16) __half g_flo[W_TOTAL];

struct Smem {
    __half a1[ROWS * LDA_ACT];     // 33792 B
    __half a2[ROWS * LDA_ACT];     // 33792 B
    float S[256];
    float t[768];                  // r/z/n gate comm terms, precomputed
};  // ~71.7 KB

// ---------------- pre-pass 1: fp32 -> fp16 hi/lo split (row-major) --------
__global__ void conv_weights(const float* __restrict__ enc, const float* __restrict__ obsw,
                             const float* __restrict__ ih,  const float* __restrict__ hh,
                             const float* __restrict__ val, const float* __restrict__ dec)
{
    int i = blockIdx.x * blockDim.x + threadIdx.x;
    if (i >= W_TOTAL) return;
    const float* src;
    int off;
    float scale = 1.0f;
    if (i < OFF_OBS)      { src = enc;  off = i; }
    else if (i < OFF_IH)  { src = obsw; off = i - OFF_OBS; }
    else if (i < OFF_HH)  { src = ih;   off = i - OFF_IH; scale = -0.015625f; }
    else if (i < OFF_VAL) { src = hh;   off = i - OFF_HH; }
    else if (i < OFF_DEC) { src = val;  off = i - OFF_VAL; }
    else                  { src = dec;  off = i - OFF_DEC; }
    float v = src[off] * scale;
    __half h = __float2half_rn(v);
    g_whi[i] = h;
    g_wlo[i] = __float2half_rn(v - __half2float(h));
}

// ---------------- pre-pass 2: row-major -> fragment-major -----------------
// Entry e (4 fp16) = lane fragment for (tile_n, ks, lane):
//   fhi[e*4..+3] = { W[row][k0], W[row][k0+1], W[row][k0+8], W[row][k0+9] }
//   with row = tile_n*8 + (lane>>2), k0 = ks*16 + 2*(lane&3).
__global__ void conv_frags()
{
    int e = blockIdx.x * blockDim.x + threadIdx.x;
    if (e >= W_TOTAL / 4) return;
    int off = e * 4;
    int base, K;
    if (off < OFF_OBS)      { base = OFF_ENC; K = 128; }
    else if (off < OFF_IH)  { base = OFF_OBS; K = 256; }
    else if (off < OFF_HH)  { base = OFF_IH;  K = 256; }
    else if (off < OFF_VAL) { base = OFF_HH;  K = 256; }
    else if (off < OFF_DEC) { base = OFF_VAL; K = 256; }
    else                    { base = OFF_DEC; K = 256; }
    int eloc = e - base / 4;
    int ksteps = K / 16;
    int tile_n = eloc / (ksteps * 32);
    int rem = eloc - tile_n * (ksteps * 32);
    int ks = rem >> 5;
    int lane = rem & 31;
    int row = tile_n * 8 + (lane >> 2);
    int k0 = ks * 16 + 2 * (lane & 3);
    const __half* sh = g_whi + base + (size_t)row * K;
    const __half* sl = g_wlo + base + (size_t)row * K;
    g_fhi[off + 0] = sh[k0];
    g_fhi[off + 1] = sh[k0 + 1];
    g_fhi[off + 2] = sh[k0 + 8];
    g_fhi[off + 3] = sh[k0 + 9];
    g_flo[off + 0] = sl[k0];
    g_flo[off + 1] = sl[k0 + 1];
    g_flo[off + 2] = sl[k0 + 8];
    g_flo[off + 3] = sl[k0 + 9];
}

// ------------------------- device helpers --------------------------------
__device__ __forceinline__ float sigm(float x) { return 1.0f / (1.0f + __expf(-x)); }

__device__ __forceinline__ void mma_f16(float* d,
                                        uint32_t a0, uint32_t a1, uint32_t a2, uint32_t a3,
                                        uint32_t b0, uint32_t b1)
{
    asm volatile("mma.sync.aligned.m16n8k16.row.col.f32.f16.f16.f32 "
                 "{%0,%1,%2,%3}, {%4,%5,%6,%7}, {%8,%9}, {%0,%1,%2,%3};\n"
                 : "+f"(d[0]), "+f"(d[1]), "+f"(d[2]), "+f"(d[3])
                 : "r"(a0), "r"(a1), "r"(a2), "r"(a3), "r"(b0), "r"(b1));
}

// Barrier-free GEMM pass: B fragments streamed global->register from the
// fragment-major layout; A fragments from smem. MT m16-tiles, NT n8-tiles.
template<int NT, int MT>
__device__ __forceinline__ void gemm_ng(const __half* __restrict__ ah,
                                        size_t fbase, int ksteps, int tile0,
                                        int lane, int g, int t4, float* acc)
{
#pragma unroll 4
    for (int ks = 0; ks < ksteps; ++ks) {
        uint32_t bh0[NT], bh1[NT], bl0[NT], bl1[NT];
#pragma unroll
        for (int nt = 0; nt < NT; ++nt) {
            size_t eb = fbase + ((size_t)((tile0 + nt) * ksteps + ks) * 32 + lane) * 4;
            uint2 fh = *(const uint2*)&g_fhi[eb];
            uint2 fl = *(const uint2*)&g_flo[eb];
            bh0[nt] = fh.x;
            bh1[nt] = fh.y;
            bl0[nt] = fl.x;
            bl1[nt] = fl.y;
        }
        int klA = ks * 16 + 2 * t4;
#pragma unroll
        for (int mt = 0; mt < MT; ++mt) {
            int ab = (mt * 16 + g) * LDA_ACT + klA;
            uint32_t A0 = *(const uint32_t*)&ah[ab];
            uint32_t A1 = *(const uint32_t*)&ah[ab + 8 * LDA_ACT];
            uint32_t A2 = *(const uint32_t*)&ah[ab + 8];
            uint32_t A3 = *(const uint32_t*)&ah[ab + 8 * LDA_ACT + 8];
#pragma unroll
            for (int nt = 0; nt < NT; ++nt) {
                float* d = acc + (mt * NT + nt) * 4;
                mma_f16(d, A0, A1, A2, A3, bh0[nt], bh1[nt]);
                mma_f16(d, A0, A1, A2, A3, bl0[nt], bl1[nt]);
            }
        }
    }
}

__device__ __forceinline__ void store_h2(__half* a, int row, int col, float v0, float v1)
{
    __half2 p;
    p.x = __float2half_rn(v0);
    p.y = __float2half_rn(v1);
    *reinterpret_cast<__half2*>(&a[row * LDA_ACT + col]) = p;
}

__device__ __forceinline__ float2 load_h2(const __half* a, int row, int col)
{
    __half2 p = *reinterpret_cast<const __half2*>(&a[row * LDA_ACT + col]);
    float2 r;
    r.x = __half2float(p.x);
    r.y = __half2float(p.y);
    return r;
}

__device__ __forceinline__ void zero32(float* a)
{
#pragma unroll
    for (int i = 0; i < 32; ++i) { a[i] = 0.0f; }
}

// ------------------------- main fused kernel -----------------------------
__global__ void __launch_bounds__(NTHREADS, 1)
commnet_mma_kernel(const float* __restrict__ obs,
                   const float* __restrict__ b_enc, const float* __restrict__ b_obs,
                   const float* __restrict__ b_ih,  const float* __restrict__ b_hh,
                   const float* __restrict__ b_val, const float* __restrict__ b_dec,
                   float* __restrict__ out)
{
    extern __shared__ char smem_raw[];
    Smem& s = *reinterpret_cast<Smem*>(smem_raw);

    const int tid  = threadIdx.x;
    const int bid  = blockIdx.x;
    const int wid  = tid >> 5;
    const int lane = tid & 31;
    const int g    = lane >> 2;
    const int t4   = lane & 3;
    const int n0g  = wid * 16;        // warp's 16-col base
    const int tile0 = wid * 2;        // warp's first n8-tile

    float acc[32];

    // ---- P1: load obs [64 x 128] -> a1 fp16 ----
    {
        const float* ob = obs + (size_t)bid * ROWS * 128;
        for (int idx = tid; idx < ROWS * 128; idx += NTHREADS) {
            int r = idx >> 7;
            int k = idx & 127;
            s.a1[r * LDA_ACT + k] = __float2half_rn(ob[idx]);
        }
    }
    __syncthreads();

    // ---- P2: x = relu(obs @ W_enc^T + b_enc) -> a2 ----
    zero32(acc);
    gemm_ng<2, 4>(s.a1, OFF_ENC, 8, tile0, lane, g, t4, acc);
    for (int mt = 0; mt < 4; ++mt) {
        for (int nt = 0; nt < 2; ++nt) {
            int col = n0g + nt * 8 + 2 * t4;
            int r0 = mt * 16 + g;
            const float* d = acc + (mt * 2 + nt) * 4;
            float b0 = __ldg(&b_enc[col]);
            float b1 = __ldg(&b_enc[col + 1]);
            store_h2(s.a2, r0, col, fmaxf(d[0] + b0, 0.0f), fmaxf(d[1] + b1, 0.0f));
            store_h2(s.a2, r0 + 8, col, fmaxf(d[2] + b0, 0.0f), fmaxf(d[3] + b1, 0.0f));
        }
    }
    __syncthreads();

    // ---- P3: h = x @ W_obs^T + b_obs -> a1 ----
    zero32(acc);
    gemm_ng<2, 4>(s.a2, OFF_OBS, 16, tile0, lane, g, t4, acc);
    for (int mt = 0; mt < 4; ++mt) {
        for (int nt = 0; nt < 2; ++nt) {
            int col = n0g + nt * 8 + 2 * t4;
            int r0 = mt * 16 + g;
            const float* d = acc + (mt * 2 + nt) * 4;
            float b0 = __ldg(&b_obs[col]);
            float b1 = __ldg(&b_obs[col + 1]);
            store_h2(s.a1, r0, col, d[0] + b0, d[1] + b1);
            store_h2(s.a1, r0 + 8, col, d[2] + b0, d[3] + b1);
        }
    }
    __syncthreads();

    // ---- P4a: S = column sums of h ----
    if (tid < 256) {
        float sum = 0.0f;
#pragma unroll 8
        for (int r = 0; r < ROWS; ++r) {
            sum += __half2float(s.a1[r * LDA_ACT + tid]);
        }
        s.S[tid] = sum;
    }
    __syncthreads();

    // ---- P4b: t[col] = S . W'_ih[col] for all 768 gate cols (once) ----
    // warp per column; lane covers 8 k's; coalesced 16B loads; shfl reduce.
    for (int col = wid; col < 768; col += 16) {
        const __half* ph = g_whi + OFF_IH + (size_t)col * 256 + lane * 8;
        const __half* pl = g_wlo + OFF_IH + (size_t)col * 256 + lane * 8;
        uint4 uh = *(const uint4*)ph;
        uint4 ul = *(const uint4*)pl;
        const __half2* hh2 = (const __half2*)&uh;
        const __half2* ll2 = (const __half2*)&ul;
        float sum = 0.0f;
#pragma unroll
        for (int j = 0; j < 4; ++j) {
            float2 wh_ = __half22float2(hh2[j]);
            float2 wl_ = __half22float2(ll2[j]);
            sum += s.S[lane * 8 + 2 * j]     * (wh_.x + wl_.x);
            sum += s.S[lane * 8 + 2 * j + 1] * (wh_.y + wl_.y);
        }
#pragma unroll
        for (int o = 16; o > 0; o >>= 1) {
            sum += __shfl_down_sync(0xFFFFFFFF, sum, o);
        }
        if (lane == 0) { s.t[col] = sum; }
    }
    __syncthreads();

    // ======== P5 GRU (r, n, z; fragments round-trip through a2) ========

    // r gate: acc = h.Whh_r + h.Wih'_r ; r = sigmoid(acc - t + b)
    zero32(acc);
    gemm_ng<2, 4>(s.a1, OFF_HH, 16, tile0, lane, g, t4, acc);
    gemm_ng<2, 4>(s.a1, OFF_IH, 16, tile0, lane, g, t4, acc);
    for (int mt = 0; mt < 4; ++mt) {
        for (int nt = 0; nt < 2; ++nt) {
            int col = n0g + nt * 8 + 2 * t4;
            int r0 = mt * 16 + g;
            float* d = acc + (mt * 2 + nt) * 4;
            float c0 = -s.t[col] + __ldg(&b_ih[col]) + __ldg(&b_hh[col]);
            float c1 = -s.t[col + 1] + __ldg(&b_ih[col + 1]) + __ldg(&b_hh[col + 1]);
            store_h2(s.a2, r0, col, sigm(d[0] + c0), sigm(d[1] + c1));
            store_h2(s.a2, r0 + 8, col, sigm(d[2] + c0), sigm(d[3] + c1));
        }
    }
    // no barrier: n-gate reads r only at own-thread fragment positions

    // n gate
    zero32(acc);
    gemm_ng<2, 4>(s.a1, OFF_HH + 512 * 256, 16, tile0, lane, g, t4, acc);
    for (int mt = 0; mt < 4; ++mt) {
        for (int nt = 0; nt < 2; ++nt) {
            int col = n0g + nt * 8 + 2 * t4;
            int r0 = mt * 16 + g;
            float* d = acc + (mt * 2 + nt) * 4;
            float b0 = __ldg(&b_hh[512 + col]);
            float b1 = __ldg(&b_hh[512 + col + 1]);
            float2 ra = load_h2(s.a2, r0, col);
            float2 rb = load_h2(s.a2, r0 + 8, col);
            d[0] = ra.x * (d[0] + b0);
            d[1] = ra.y * (d[1] + b1);
            d[2] = rb.x * (d[2] + b0);
            d[3] = rb.y * (d[3] + b1);
        }
    }
    gemm_ng<2, 4>(s.a1, OFF_IH + 512 * 256, 16, tile0, lane, g, t4, acc);
    for (int mt = 0; mt < 4; ++mt) {
        for (int nt = 0; nt < 2; ++nt) {
            int col = n0g + nt * 8 + 2 * t4;
            int r0 = mt * 16 + g;
            float* d = acc + (mt * 2 + nt) * 4;
            float c0 = -s.t[512 + col] + __ldg(&b_ih[512 + col]);
            float c1 = -s.t[512 + col + 1] + __ldg(&b_ih[512 + col + 1]);
            store_h2(s.a2, r0, col, tanhf(d[0] + c0), tanhf(d[1] + c1));
            store_h2(s.a2, r0 + 8, col, tanhf(d[2] + c0), tanhf(d[3] + c1));
        }
    }

    // z gate + blend: h_new = (1-z)*n + z*h_old -> a2
    zero32(acc);
    gemm_ng<2, 4>(s.a1, OFF_HH + 256 * 256, 16, tile0, lane, g, t4, acc);
    gemm_ng<2, 4>(s.a1, OFF_IH + 256 * 256, 16, tile0, lane, g, t4, acc);
    for (int mt = 0; mt < 4; ++mt) {
        for (int nt = 0; nt < 2; ++nt) {
            int col = n0g + nt * 8 + 2 * t4;
            int r0 = mt * 16 + g;
            float* d = acc + (mt * 2 + nt) * 4;
            float c0 = -s.t[256 + col] + __ldg(&b_ih[256 + col]) + __ldg(&b_hh[256 + col]);
            float c1 = -s.t[256 + col + 1] + __ldg(&b_ih[256 + col + 1]) + __ldg(&b_hh[256 + col + 1]);
            float z0 = sigm(d[0] + c0);
            float z1 = sigm(d[1] + c1);
            float z2 = sigm(d[2] + c0);
            float z3 = sigm(d[3] + c1);
            float2 na = load_h2(s.a2, r0, col);
            float2 nb = load_h2(s.a2, r0 + 8, col);
            float2 ha = load_h2(s.a1, r0, col);
            float2 hb = load_h2(s.a1, r0 + 8, col);
            store_h2(s.a2, r0, col,
                     (1.0f - z0) * na.x + z0 * ha.x,
                     (1.0f - z1) * na.y + z1 * ha.y);
            store_h2(s.a2, r0 + 8, col,
                     (1.0f - z2) * nb.x + z2 * hb.x,
                     (1.0f - z3) * nb.y + z3 * hb.y);
        }
    }
    __syncthreads();   // P6 reads all of a2

    // ---- P6: v = h_new @ W_val^T + b_val -> a1 ----
    zero32(acc);
    gemm_ng<2, 4>(s.a2, OFF_VAL, 16, tile0, lane, g, t4, acc);
    for (int mt = 0; mt < 4; ++mt) {
        for (int nt = 0; nt < 2; ++nt) {
            int col = n0g + nt * 8 + 2 * t4;
            int r0 = mt * 16 + g;
            const float* d = acc + (mt * 2 + nt) * 4;
            float b0 = __ldg(&b_val[col]);
            float b1 = __ldg(&b_val[col + 1]);
            store_h2(s.a1, r0, col, d[0] + b0, d[1] + b1);
            store_h2(s.a1, r0 + 8, col, d[2] + b0, d[3] + b1);
        }
    }
    __syncthreads();   // P7 reads all of a1

    // ---- P7: out = v @ W_dec^T + b_dec (64 cols; warps 0..7, 1 tile each) ----
    if (wid < 8) {
        float ad[16];
#pragma unroll
        for (int i = 0; i < 16; ++i) { ad[i] = 0.0f; }
        gemm_ng<1, 4>(s.a1, OFF_DEC, 16, wid, lane, g, t4, ad);
        float* out_b = out + (size_t)bid * ROWS * 64;
        int col = wid * 8 + 2 * t4;
        float b0 = __ldg(&b_dec[col]);
        float b1 = __ldg(&b_dec[col + 1]);
        for (int mt = 0; mt < 4; ++mt) {
            int r0 = mt * 16 + g;
            const float* d = ad + mt * 4;
            float2 o0 = make_float2(d[0] + b0, d[1] + b1);
            float2 o1 = make_float2(d[2] + b0, d[3] + b1);
            *reinterpret_cast<float2*>(&out_b[r0 * 64 + col]) = o0;
            *reinterpret_cast<float2*>(&out_b[(r0 + 8) * 64 + col]) = o1;
        }
    }
}

extern "C" void kernel_launch(void* const* d_in, const int* in_sizes, int n_in,
                              void* d_out, int out_size)
{
    const float* obs   = (const float*)d_in[0];
    const float* W_enc = (const float*)d_in[1];
    const float* b_enc = (const float*)d_in[2];
    const float* W_obs = (const float*)d_in[3];
    const float* b_obs = (const float*)d_in[4];
    const float* W_ih  = (const float*)d_in[5];
    const float* b_ih  = (const float*)d_in[6];
    const float* W_hh  = (const float*)d_in[7];
    const float* b_hh  = (const float*)d_in[8];
    const float* W_val = (const float*)d_in[9];
    const float* b_val = (const float*)d_in[10];
    const float* W_dec = (const float*)d_in[11];
    const float* b_dec = (const float*)d_in[12];
    float* out = (float*)d_out;
    (void)in_sizes; (void)n_in; (void)out_size;

    conv_weights<<<(W_TOTAL + 255) / 256, 256>>>(W_enc, W_obs, W_ih, W_hh, W_val, W_dec);
    conv_frags<<<(W_TOTAL / 4 + 255) / 256, 256>>>();

    cudaFuncSetAttribute(commnet_mma_kernel,
                         cudaFuncAttributeMaxDynamicSharedMemorySize, (int)sizeof(Smem));
    commnet_mma_kernel<<<256, NTHREADS, sizeof(Smem)>>>(
        obs, b_enc, b_obs, b_ih, b_hh, b_val, b_dec, out);
}